// round 1
// baseline (speedup 1.0000x reference)
#include <cuda_runtime.h>
#include <math.h>

#define T_LEN 2048
#define BATCH 64
#define EMB   100
#define HID   128
#define G3    384   // 3*HID gate rows
#define NS    6     // CRF states

// ---------------- device scratch (no allocation allowed) ----------------
__device__ float g_gi[2][T_LEN][G3];        // precomputed x@Wih^T + bih, per dir
__device__ float g_hout[2][T_LEN][HID];     // GRU hidden outputs, per dir
__device__ __align__(16) float g_logits[T_LEN * NS];  // softmax probs

// ---------------- f32x2 helpers (packed dual-FP32 FMA, sm_100+) ---------
__device__ __forceinline__ unsigned long long ffma2(unsigned long long a,
                                                    unsigned long long b,
                                                    unsigned long long c) {
    unsigned long long d;
    asm("fma.rn.f32x2 %0, %1, %2, %3;" : "=l"(d) : "l"(a), "l"(b), "l"(c));
    return d;
}
__device__ __forceinline__ unsigned long long pack2(float lo, float hi) {
    unsigned long long d;
    asm("mov.b64 %0, {%1, %2};" : "=l"(d) : "f"(lo), "f"(hi));
    return d;
}
__device__ __forceinline__ float2 unpack2(unsigned long long u) {
    float2 r;
    asm("mov.b64 {%0, %1}, %2;" : "=f"(r.x), "=f"(r.y) : "l"(u));
    return r;
}

__device__ __forceinline__ float sigmoidf_(float x) {
    return 1.0f / (1.0f + expf(-x));
}

// ================= Kernel 1: gi = x @ Wih^T + bih (batch row 63) =========
// grid (512, 2), block 384. Each block: 4 timesteps for one direction.
__global__ void __launch_bounds__(G3) gi_kernel(
    const int* __restrict__ sentence, const float* __restrict__ emb,
    const float* __restrict__ Wf_ih, const float* __restrict__ bf_ih,
    const float* __restrict__ Wb_ih, const float* __restrict__ bb_ih)
{
    const int dir = blockIdx.y;
    const int t0  = blockIdx.x * 4;
    __shared__ float x_s[4][EMB];

    for (int i = threadIdx.x; i < 4 * EMB; i += G3) {
        int tt = i / EMB, e = i % EMB;
        int tok = sentence[63 * T_LEN + t0 + tt];
        x_s[tt][e] = emb[tok * EMB + e];
    }
    __syncthreads();

    const float* W = dir ? Wb_ih : Wf_ih;
    const float* b = dir ? bb_ih : bf_ih;
    const int j = threadIdx.x;

    float bj = b[j];
    float a0 = bj, a1 = bj, a2 = bj, a3 = bj;
    const float* Wr = W + j * EMB;
#pragma unroll
    for (int e = 0; e < EMB; e++) {
        float w = __ldg(Wr + e);
        a0 += w * x_s[0][e];
        a1 += w * x_s[1][e];
        a2 += w * x_s[2][e];
        a3 += w * x_s[3][e];
    }
    g_gi[dir][t0 + 0][j] = a0;
    g_gi[dir][t0 + 1][j] = a1;
    g_gi[dir][t0 + 2][j] = a2;
    g_gi[dir][t0 + 3][j] = a3;
}

// ================= Kernel 2: sequential GRU recurrence ====================
// grid 2 (direction), block 384 (one gate-row per thread).
// Weight row held in 64 packed f32x2 registers; h broadcast from SMEM.
__global__ void __launch_bounds__(G3, 1) gru_kernel(
    const float* __restrict__ Wf_hh, const float* __restrict__ bf_hh,
    const float* __restrict__ Wb_hh, const float* __restrict__ bb_hh,
    const float* __restrict__ h0)
{
    const int dir = blockIdx.x;
    const int j   = threadIdx.x;

    __shared__ __align__(16) float h_s[HID];
    __shared__ float r_s[HID];
    __shared__ float z_s[HID];

    const float* Whh = dir ? Wb_hh : Wf_hh;
    const float* bhh = dir ? bb_hh : bf_hh;

    // load weight row j into registers as 64 packed f32x2
    unsigned long long w[64];
    {
        const unsigned long long* Wrow =
            reinterpret_cast<const unsigned long long*>(Whh + j * HID);
#pragma unroll
        for (int k = 0; k < 64; k++) w[k] = __ldg(Wrow + k);
    }
    const float bias = bhh[j];

    if (j < HID) h_s[j] = h0[dir * (BATCH * HID) + 63 * HID + j];
    __syncthreads();

    const float* gi   = &g_gi[dir][0][0];
    float*       hout = &g_hout[dir][0][0];

    const int tstep = dir ? -1 : 1;
    int t = dir ? (T_LEN - 1) : 0;
    float g_cur = __ldg(gi + t * G3 + j);

    for (int s = 0; s < T_LEN; s++) {
        // prefetch next step's gi (hides L2 latency behind the matvec)
        float g_next = 0.0f;
        if (s + 1 < T_LEN) g_next = __ldg(gi + (t + tstep) * G3 + j);

        // gh_j = Whh[j,:] . h + bhh[j]   (packed dual-FP32 FMAs)
        unsigned long long a0 = pack2(bias, 0.0f);
        unsigned long long a1 = 0ull, a2 = 0ull, a3 = 0ull;
        const ulonglong2* h2 = reinterpret_cast<const ulonglong2*>(h_s);
#pragma unroll
        for (int q = 0; q < 16; q++) {
            ulonglong2 hv0 = h2[2 * q];
            ulonglong2 hv1 = h2[2 * q + 1];
            a0 = ffma2(w[4 * q + 0], hv0.x, a0);
            a1 = ffma2(w[4 * q + 1], hv0.y, a1);
            a2 = ffma2(w[4 * q + 2], hv1.x, a2);
            a3 = ffma2(w[4 * q + 3], hv1.y, a3);
        }
        float2 f0 = unpack2(a0), f1 = unpack2(a1);
        float2 f2 = unpack2(a2), f3 = unpack2(a3);
        float gh = ((f0.x + f0.y) + (f1.x + f1.y)) +
                   ((f2.x + f2.y) + (f3.x + f3.y));

        if (j < HID) {                      // r gate
            r_s[j] = sigmoidf_(g_cur + gh);
        } else if (j < 2 * HID) {           // z gate
            z_s[j - HID] = sigmoidf_(g_cur + gh);
        }
        __syncthreads();
        if (j >= 2 * HID) {                 // n gate + state update
            int jj = j - 2 * HID;
            float n    = tanhf(g_cur + r_s[jj] * gh);
            float hold = h_s[jj];
            float hnew = n + z_s[jj] * (hold - n);   // (1-z)*n + z*h
            h_s[jj] = hnew;
            hout[t * HID + jj] = hnew;
        }
        __syncthreads();

        g_cur = g_next;
        t += tstep;
    }
}

// ============ Kernel 3: output projection + softmax (per timestep) ========
// grid 2048, block 192 (warp s computes state s).
__global__ void __launch_bounds__(192) proj_kernel(
    const float* __restrict__ W_out, const float* __restrict__ b_out)
{
    const int t    = blockIdx.x;
    const int wid  = threadIdx.x >> 5;   // state 0..5
    const int lane = threadIdx.x & 31;
    __shared__ float lg_s[NS];

    float acc = 0.0f;
    const float* Wr = W_out + wid * (2 * HID);
#pragma unroll
    for (int i = lane; i < 2 * HID; i += 32) {
        float c = (i < HID) ? g_hout[0][t][i] : g_hout[1][t][i - HID];
        acc += c * __ldg(Wr + i);
    }
#pragma unroll
    for (int off = 16; off; off >>= 1)
        acc += __shfl_xor_sync(0xFFFFFFFFu, acc, off);
    if (lane == 0) lg_s[wid] = acc + b_out[wid];
    __syncthreads();

    if (threadIdx.x == 0) {
        float m = lg_s[0];
#pragma unroll
        for (int i = 1; i < NS; i++) m = fmaxf(m, lg_s[i]);
        float e[NS];
        float sum = 0.0f;
#pragma unroll
        for (int i = 0; i < NS; i++) { e[i] = expf(lg_s[i] - m); sum += e[i]; }
        float inv = 1.0f / sum;
#pragma unroll
        for (int i = 0; i < NS; i++) g_logits[t * NS + i] = e[i] * inv;
    }
}

// ================= Kernel 4: Viterbi (single warp) =========================
// dynamic smem: logits (49152B) + backpointers (2047*6 bytes)
__global__ void viterbi_kernel(const float* __restrict__ transitions,
                               float* __restrict__ out, int out_size)
{
    extern __shared__ char sm[];
    float*         lg_sh = (float*)sm;
    unsigned char* bp_sh = (unsigned char*)(sm + T_LEN * NS * 4);
    const int lane = threadIdx.x;

    // stage all logits into SMEM (vectorized)
    {
        const float4* src = (const float4*)g_logits;
        float4*       dst = (float4*)lg_sh;
        for (int i = lane; i < T_LEN * NS / 4; i += 32) dst[i] = src[i];
    }
    __syncwarp();

    float Tc[NS];
#pragma unroll
    for (int i = 0; i < NS; i++)
        Tc[i] = (lane < NS) ? transitions[i * NS + lane] : 0.0f;

    float tr = (lane < NS) ? lg_sh[lane] : -1e30f;

    for (int t = 1; t < T_LEN; t++) {
        float lg = lg_sh[t * NS + ((lane < NS) ? lane : 0)];
        float trg[NS];
#pragma unroll
        for (int i = 0; i < NS; i++)
            trg[i] = __shfl_sync(0xFFFFFFFFu, tr, i);
        float best = trg[0] + Tc[0];
        int   bi   = 0;
#pragma unroll
        for (int i = 1; i < NS; i++) {
            float v = trg[i] + Tc[i];
            if (v > best) { best = v; bi = i; }   // strict >  => first argmax
        }
        if (lane < NS) {
            bp_sh[(t - 1) * NS + lane] = (unsigned char)bi;
            tr = lg + best;
        }
    }

    // final score + argmax (first max wins, matching jnp.argmax)
    float fin[NS];
#pragma unroll
    for (int i = 0; i < NS; i++) fin[i] = __shfl_sync(0xFFFFFFFFu, tr, i);
    float score = fin[0];
    int   last  = 0;
#pragma unroll
    for (int i = 1; i < NS; i++)
        if (fin[i] > score) { score = fin[i]; last = i; }

    if (lane == 0) {
        out[0] = score;
        int idx = last;
        out[1 + (T_LEN - 1)] = (float)idx;
        for (int t = T_LEN - 2; t >= 0; t--) {
            idx = bp_sh[t * NS + idx];
            out[1 + t] = (float)idx;
        }
    }
    __syncwarp();
    // zero any padding beyond [score, path]
    for (int i = T_LEN + 1 + lane; i < out_size; i += 32) out[i] = 0.0f;
}

// ============================ launch =======================================
extern "C" void kernel_launch(void* const* d_in, const int* in_sizes, int n_in,
                              void* d_out, int out_size) {
    const int*   sentence    = (const int*)d_in[0];
    const float* emb         = (const float*)d_in[1];
    const float* h0          = (const float*)d_in[2];
    const float* Wf_ih       = (const float*)d_in[3];
    const float* Wf_hh       = (const float*)d_in[4];
    const float* bf_ih       = (const float*)d_in[5];
    const float* bf_hh       = (const float*)d_in[6];
    const float* Wb_ih       = (const float*)d_in[7];
    const float* Wb_hh       = (const float*)d_in[8];
    const float* bb_ih       = (const float*)d_in[9];
    const float* bb_hh       = (const float*)d_in[10];
    const float* W_out       = (const float*)d_in[11];
    const float* b_out       = (const float*)d_in[12];
    const float* transitions = (const float*)d_in[13];
    float*       out         = (float*)d_out;

    const int vit_smem = T_LEN * NS * 4 + (T_LEN - 1) * NS;  // 61434 B
    cudaFuncSetAttribute(viterbi_kernel,
                         cudaFuncAttributeMaxDynamicSharedMemorySize, vit_smem);

    gi_kernel<<<dim3(T_LEN / 4, 2), G3>>>(sentence, emb, Wf_ih, bf_ih,
                                          Wb_ih, bb_ih);
    gru_kernel<<<2, G3>>>(Wf_hh, bf_hh, Wb_hh, bb_hh, h0);
    proj_kernel<<<T_LEN, 192>>>(W_out, b_out);
    viterbi_kernel<<<1, 32, vit_smem>>>(transitions, out, out_size);
}